// round 8
// baseline (speedup 1.0000x reference)
#include <cuda_runtime.h>
#include <cstdint>
#include <cstddef>

#define BR   4096
#define MF   20000
#define EMB  100
#define NPAD 128
#define KC   32
#define NCHT 625            // 20000/32 exactly
#define EPSB 1e-5f
#define STG  24576          // Ah 4K | Al 4K | Wh 8K | Wl 8K
#define NSTG 3

typedef unsigned long long u64;
typedef unsigned int u32;

// ---------------- device scratch ----------------
__device__ int   g_mode;                       // 0=int32, 1=byte bool, 2=float32
__device__ unsigned short g_Wh[NPAD * MF];     // bf16 hi split, rows 100..127 zero
__device__ unsigned short g_Wl[NPAD * MF];     // bf16 lo split
__device__ float g_Part[4][2][BR][104];        // ksplit, pass, row, col
__device__ float g_H1[2 * BR * EMB];
__device__ float g_H2[2 * BR * EMB];
__device__ float g_H3[2 * BR * EMB];
__device__ float g_P[3][2][128][2][EMB];
__device__ float g_bns[3][2][EMB];
__device__ float g_bnb[3][2][EMB];

// ---------------- helpers ----------------
__device__ __forceinline__ u32 smem_u32(const void* p) {
    u32 a; asm("{ .reg .u64 t; cvta.to.shared.u64 t, %1; cvt.u32.u64 %0, t; }" : "=r"(a) : "l"(p));
    return a;
}
__device__ __forceinline__ void ldsm4(u32& r0, u32& r1, u32& r2, u32& r3, u32 addr) {
    asm volatile("ldmatrix.sync.aligned.m8n8.x4.shared.b16 {%0,%1,%2,%3}, [%4];"
        : "=r"(r0), "=r"(r1), "=r"(r2), "=r"(r3) : "r"(addr));
}
__device__ __forceinline__ void mma16816(float* d, const u32* a, const u32* b) {
    asm volatile("mma.sync.aligned.m16n8k16.row.col.f32.bf16.bf16.f32 "
        "{%0,%1,%2,%3}, {%4,%5,%6,%7}, {%8,%9}, {%0,%1,%2,%3};"
        : "+f"(d[0]), "+f"(d[1]), "+f"(d[2]), "+f"(d[3])
        : "r"(a[0]), "r"(a[1]), "r"(a[2]), "r"(a[3]), "r"(b[0]), "r"(b[1]));
}
__device__ __forceinline__ void cp16(u32 dst, const void* src) {
    asm volatile("cp.async.cg.shared.global [%0], [%1], 16;"
        :: "r"(dst), "l"(src) : "memory");
}
#define CP_COMMIT() asm volatile("cp.async.commit_group;" ::: "memory")
#define CP_WAIT1()  asm volatile("cp.async.wait_group 1;" ::: "memory")
#define CP_WAIT0()  asm volatile("cp.async.wait_group 0;" ::: "memory")

// 64B-row swizzle: byte col16 XOR'd by row bits 1..2
__device__ __forceinline__ u32 sw64(u32 row, u32 colb) {
    return row * 64 + (colb ^ (((row >> 1) & 3) << 4));
}
// bf16 split
__device__ __forceinline__ u32 prmt_hi(float a, float b) {
    u32 r; asm("prmt.b32 %0, %1, %2, 0x7632;" : "=r"(r)
               : "r"(__float_as_uint(a)), "r"(__float_as_uint(b)));
    return r;
}
__device__ __forceinline__ u32 pk_lo(float a, float b) {
    float la = a - __uint_as_float(__float_as_uint(a) & 0xffff0000u);
    float lb = b - __uint_as_float(__float_as_uint(b) & 0xffff0000u);
    u32 r; asm("cvt.rn.bf16x2.f32 %0, %1, %2;" : "=r"(r) : "f"(lb), "f"(la));
    return r;
}
// packed f32x2
__device__ __forceinline__ u64 pk2(float lo, float hi) {
    u64 d; asm("mov.b64 %0, {%1, %2};" : "=l"(d) : "f"(lo), "f"(hi)); return d;
}
__device__ __forceinline__ u64 fma2(u64 a, u64 b, u64 c) {
    u64 d; asm("fma.rn.f32x2 %0, %1, %2, %3;" : "=l"(d) : "l"(a), "l"(b), "l"(c)); return d;
}
__device__ __forceinline__ float2 upk2(u64 v) {
    float2 r; asm("mov.b64 {%0, %1}, %2;" : "=f"(r.x), "=f"(r.y) : "l"(v)); return r;
}

// ---------------- mask dtype classifier ----------------
__global__ void k_detect(const unsigned char* __restrict__ m) {
    __shared__ int s_nz, s_gt;
    if (threadIdx.x == 0) { s_nz = 0; s_gt = 0; }
    __syncthreads();
    int nz = 0, gt = 0;
    for (int i = threadIdx.x; i < 65536; i += blockDim.x) {
        unsigned char v = m[i];
        nz += (v != 0); gt += (v > 1);
    }
    atomicAdd(&s_nz, nz); atomicAdd(&s_gt, gt);
    __syncthreads();
    if (threadIdx.x == 0)
        g_mode = (s_gt > 64) ? 2 : (s_nz > 24576) ? 1 : 0;
}

// ---------------- W split precompute ----------------
__global__ void k_wcvt(const float* __restrict__ w, int base) {
    int i = base + blockIdx.x * blockDim.x + threadIdx.x;
    if (i >= NPAD * MF / 2) return;
    int row = i / (MF / 2), within = i % (MF / 2);
    if (row < EMB) {
        float2 v = *(const float2*)(w + (size_t)row * MF + 2 * within);
        ((u32*)g_Wh)[i] = prmt_hi(v.x, v.y);
        ((u32*)g_Wl)[i] = pk_lo(v.x, v.y);
    } else {
        ((u32*)g_Wh)[i] = 0u;
        ((u32*)g_Wl)[i] = 0u;
    }
}

// ---------------- Layer 1: split-bf16 mma.sync, 3-stage, 3 CTAs/SM ----------
// grid=512: p = bid&1, ks4 = (bid>>1)&3, tile = bid>>3 (64 rows).
// Stage (24KB): Ah@0 | Al@4K | Wh@8K | Wl@16K. Rows are 64B (KC=32 bf16).
__global__ __launch_bounds__(256, 3)
void k_big(const float* __restrict__ x, const void* __restrict__ mk,
           const float* __restrict__ xr)
{
    extern __shared__ char smem[];
    const u32 sb = smem_u32(smem);
    const int t = threadIdx.x;
    const int w = t >> 5, lane = t & 31;
    const int p = blockIdx.x & 1, ks4 = (blockIdx.x >> 1) & 3, tile = blockIdx.x >> 3;
    const int r0g = tile * 64;
    const int ci0 = ks4 ? (157 + 156 * (ks4 - 1)) : 0;
    const int n   = ks4 ? 156 : 157;
    const int wm = w >> 2, nc = w & 3;
    const int mode = g_mode;

    // A staging: one 16B chunk per thread per split: arow = t>>2, seg = t&3
    const int arow = t >> 2, seg = t & 3;
    const size_t abase = (size_t)(r0g + arow) * MF + (size_t)(ci0 * KC) + seg * 8;
    const u32 aoff = sw64(arow, seg * 16);

    // W cp.async: 2 chunks of 16B per thread per split
    u32 woff0, woff1; size_t wsrc0, wsrc1;
    {
        int g0 = t, g1 = t + 256;
        int r0w = g0 >> 2, s0 = g0 & 3, r1w = g1 >> 2, s1 = g1 & 3;
        woff0 = sw64(r0w, s0 * 16);
        woff1 = sw64(r1w, s1 * 16);
        wsrc0 = (size_t)r0w * MF + (size_t)(ci0 * KC) + s0 * 8;
        wsrc1 = (size_t)r1w * MF + (size_t)(ci0 * KC) + s1 * 8;
    }

    uint4 HA, LA;
    float acc[2][4][4];
    #pragma unroll
    for (int mf = 0; mf < 2; mf++)
        #pragma unroll
        for (int nf = 0; nf < 4; nf++)
            #pragma unroll
            for (int e = 0; e < 4; e++) acc[mf][nf][e] = 0.f;

    auto CPW = [&](int j) {           // local chunk j -> stage j%3
        const u32 base = sb + (j % 3) * STG;
        const size_t ko = (size_t)j * KC;
        cp16(base +  8192 + woff0, g_Wh + wsrc0 + ko);
        cp16(base +  8192 + woff1, g_Wh + wsrc1 + ko);
        cp16(base + 16384 + woff0, g_Wl + wsrc0 + ko);
        cp16(base + 16384 + woff1, g_Wl + wsrc1 + ko);
    };

    auto STAGE = [&](int j) {
        const size_t g = abase + (size_t)j * KC;
        float v[8];
        float4 x0 = *(const float4*)(x + g);
        float4 x1 = *(const float4*)(x + g + 4);
        v[0]=x0.x; v[1]=x0.y; v[2]=x0.z; v[3]=x0.w;
        v[4]=x1.x; v[5]=x1.y; v[6]=x1.z; v[7]=x1.w;
        if (p == 1) {
            float4 q0 = *(const float4*)(xr + g);
            float4 q1 = *(const float4*)(xr + g + 4);
            float q[8] = {q0.x,q0.y,q0.z,q0.w,q1.x,q1.y,q1.z,q1.w};
            if (mode == 1) {
                uint2 mm = *(const uint2*)((const unsigned char*)mk + g);
                u32 lo = mm.x, hi = mm.y;
                #pragma unroll
                for (int m = 0; m < 4; m++) {
                    if ((lo >> (m*8)) & 0xff) v[m]   = q[m];
                    if ((hi >> (m*8)) & 0xff) v[m+4] = q[m+4];
                }
            } else if (mode == 0) {
                int4 m0 = *(const int4*)((const int*)mk + g);
                int4 m1 = *(const int4*)((const int*)mk + g + 4);
                int mi[8] = {m0.x,m0.y,m0.z,m0.w,m1.x,m1.y,m1.z,m1.w};
                #pragma unroll
                for (int m = 0; m < 8; m++) if (mi[m]) v[m] = q[m];
            } else {
                float4 m0 = *(const float4*)((const float*)mk + g);
                float4 m1 = *(const float4*)((const float*)mk + g + 4);
                float mf_[8] = {m0.x,m0.y,m0.z,m0.w,m1.x,m1.y,m1.z,m1.w};
                #pragma unroll
                for (int m = 0; m < 8; m++) if (mf_[m] != 0.f) v[m] = q[m];
            }
        }
        HA.x = prmt_hi(v[0],v[1]); HA.y = prmt_hi(v[2],v[3]);
        HA.z = prmt_hi(v[4],v[5]); HA.w = prmt_hi(v[6],v[7]);
        LA.x = pk_lo (v[0],v[1]); LA.y = pk_lo (v[2],v[3]);
        LA.z = pk_lo (v[4],v[5]); LA.w = pk_lo (v[6],v[7]);
    };

    auto STORE_A = [&](int j) {
        char* bs = smem + (j % 3) * STG;
        *(uint4*)(bs +        aoff) = HA;
        *(uint4*)(bs + 4096 + aoff) = LA;
    };

    // COMP lane addressing
    const u32 rowa = wm * 32 + (lane & 15);
    const u32 c16A = ((lane >> 4) & 1) * 16;
    const u32 xrA = ((rowa >> 1) & 3) << 4;
    const u32 baseA0 = rowa * 64;             // mf0
    const u32 baseA1 = (rowa + 16) * 64;      // mf1
    const u32 xrA1 = (((rowa + 16) >> 1) & 3) << 4;
    const u32 nrow = nc * 32 + ((lane >> 4) & 1) * 8 + (lane & 7);
    const u32 c16B = ((lane >> 3) & 1) * 16;
    const u32 baseB0 = nrow * 64,        xrB0 = ((nrow >> 1) & 3) << 4;
    const u32 baseB1 = (nrow + 16) * 64, xrB1 = (((nrow + 16) >> 1) & 3) << 4;

    auto COMP = [&](int j) {
        const u32 bs = sb + (j % 3) * STG;
        const u32 Ah = bs, Al = bs + 4096, Wh = bs + 8192, Wl = bs + 16384;
        #pragma unroll
        for (int ks = 0; ks < 2; ks++) {
            const u32 kb = ks * 32;
            u32 aH[2][4], aL[2][4], bH[4][2], bL[4][2];
            ldsm4(aH[0][0], aH[0][1], aH[0][2], aH[0][3], Ah + baseA0 + ((kb + c16A) ^ xrA));
            ldsm4(aH[1][0], aH[1][1], aH[1][2], aH[1][3], Ah + baseA1 + ((kb + c16A) ^ xrA1));
            ldsm4(aL[0][0], aL[0][1], aL[0][2], aL[0][3], Al + baseA0 + ((kb + c16A) ^ xrA));
            ldsm4(aL[1][0], aL[1][1], aL[1][2], aL[1][3], Al + baseA1 + ((kb + c16A) ^ xrA1));
            ldsm4(bH[0][0], bH[0][1], bH[1][0], bH[1][1], Wh + baseB0 + ((kb + c16B) ^ xrB0));
            ldsm4(bH[2][0], bH[2][1], bH[3][0], bH[3][1], Wh + baseB1 + ((kb + c16B) ^ xrB1));
            ldsm4(bL[0][0], bL[0][1], bL[1][0], bL[1][1], Wl + baseB0 + ((kb + c16B) ^ xrB0));
            ldsm4(bL[2][0], bL[2][1], bL[3][0], bL[3][1], Wl + baseB1 + ((kb + c16B) ^ xrB1));
            #pragma unroll
            for (int mf = 0; mf < 2; mf++)
                #pragma unroll
                for (int nf = 0; nf < 4; nf++) {
                    mma16816(acc[mf][nf], aH[mf], bH[nf]);
                    mma16816(acc[mf][nf], aH[mf], bL[nf]);
                    mma16816(acc[mf][nf], aL[mf], bH[nf]);
                }
        }
    };

    // prologue
    CPW(0); CP_COMMIT();
    CPW(1); CP_COMMIT();
    STAGE(0);
    CP_WAIT1();                  // W(0) arrived
    STORE_A(0);
    __syncthreads();
    STAGE(1);

    for (int i = 0; i < n; i++) {
        if (i + 1 < n) STORE_A(i + 1);    // regs staged at end of prev iter
        COMP(i);
        if (i + 2 < n) { CPW(i + 2); CP_COMMIT(); CP_WAIT1(); }
        else if (i + 1 < n) CP_WAIT0();
        __syncthreads();
        if (i + 2 < n) STAGE(i + 2);
    }

    // epilogue: raw partials -> g_Part
    float* Pp = &g_Part[ks4][p][0][0];
    const int gq = lane >> 2, tt = lane & 3;
    #pragma unroll
    for (int mf = 0; mf < 2; mf++)
        #pragma unroll
        for (int nf = 0; nf < 4; nf++) {
            const int col = nc * 32 + nf * 8 + 2 * tt;
            if (col < EMB) {
                const int ra = r0g + wm * 32 + mf * 16 + gq;
                *(float2*)&Pp[(size_t)ra * 104 + col] =
                    make_float2(acc[mf][nf][0], acc[mf][nf][1]);
                *(float2*)&Pp[(size_t)(ra + 8) * 104 + col] =
                    make_float2(acc[mf][nf][2], acc[mf][nf][3]);
            }
        }
}

// ---------------- merge K-splits: bias + relu -> H1 + BN partials ----------
__global__ void k_merge(const float* __restrict__ bias) {
    __shared__ float Ds[64][104];
    const int t = threadIdx.x, tile = blockIdx.x, p = blockIdx.y;
    const int r = t >> 2, cg = t & 3;
    const size_t row = (size_t)tile * 64 + r;
    #pragma unroll
    for (int j = 0; j < 25; j++) {
        const int c = cg * 25 + j;
        float v = g_Part[0][p][row][c] + g_Part[1][p][row][c]
                + g_Part[2][p][row][c] + g_Part[3][p][row][c] + bias[c];
        v = fmaxf(v, 0.f);
        g_H1[((size_t)p * BR + row) * EMB + c] = v;
        Ds[r][c] = v;
    }
    __syncthreads();
    if (t < EMB) {
        float s = 0.f, s2 = 0.f;
        #pragma unroll 8
        for (int rr = 0; rr < 64; rr++) { float u = Ds[rr][t]; s += u; s2 += u * u; }
        g_P[0][p][tile][0][t] = s;
        g_P[0][p][tile][1][t] = s2;
    }
}

// ---------------- BN stats ----------------
__global__ void k_stats(int stage, const float* __restrict__ g,
                        const float* __restrict__ be, int ntiles)
{
    __shared__ float sred[2][2][EMB];
    const int p = blockIdx.x, t = threadIdx.x;
    const int c = t & 127, half = t >> 7;
    const int cnt = ntiles >> 1;
    if (c < EMB) {
        float a0 = 0.f, a1 = 0.f, b0 = 0.f, b1 = 0.f;
        const int base = half * cnt;
        for (int i = 0; i < cnt; i += 2) {
            a0 += g_P[stage][p][base + i][0][c];
            a1 += g_P[stage][p][base + i + 1][0][c];
            b0 += g_P[stage][p][base + i][1][c];
            b1 += g_P[stage][p][base + i + 1][1][c];
        }
        sred[half][0][c] = a0 + a1;
        sred[half][1][c] = b0 + b1;
    }
    __syncthreads();
    if (t < EMB) {
        float s1 = sred[0][0][t] + sred[1][0][t];
        float s2 = sred[0][1][t] + sred[1][1][t];
        float mu  = s1 * (1.f / BR);
        float var = s2 * (1.f / BR) - mu * mu;
        float sc  = g[t] * rsqrtf(var + EPSB);
        g_bns[stage][p][t] = sc;
        g_bnb[stage][p][t] = be[t] - mu * sc;
    }
}

// ---------------- Layers 2-4 ----------------
__global__ __launch_bounds__(256, 1)
void k_small(int layer, const float* __restrict__ W,
             const float* __restrict__ bias, float* __restrict__ dout)
{
    extern __shared__ float sm[];
    float* Hs  = sm;            // 100*33
    float* Ws  = sm + 3300;     // 100*132
    float* red = sm + 16500;    // 2048
    float* sc  = sm + 18548;
    float* sh  = sm + 18676;

    const int t = threadIdx.x, tile = blockIdx.x, p = blockIdx.y;
    const int r0 = tile * 32;
    const int ty = t >> 4, tx = t & 15;
    const float* Hin = (layer == 0) ? g_H1 : (layer == 1) ? g_H2 : g_H3;
    const bool rin = (layer == 2), rout = (layer == 0);

    if (t < EMB) { sc[t] = g_bns[layer][p][t]; sh[t] = g_bnb[layer][p][t]; }
    __syncthreads();

    const float* Hp = Hin + (size_t)p * BR * EMB;
    for (int i = t; i < 32 * EMB; i += 256) {
        int row = i / EMB, k = i % EMB;
        float v = Hp[(size_t)(r0 + row) * EMB + k] * sc[k] + sh[k];
        if (rin) v = fmaxf(v, 0.f);
        Hs[k * 33 + row] = v;
    }
    for (int i = t; i < EMB * EMB; i += 256) {
        int nn = i / EMB, k = i % EMB;
        Ws[k * 132 + nn] = W[i];
    }
    for (int i = t; i < EMB * 28; i += 256) {
        int k = i / 28, nn = 100 + i % 28;
        Ws[k * 132 + nn] = 0.f;
    }
    __syncthreads();

    u64 acc[2][4];
    #pragma unroll
    for (int r = 0; r < 2; r++)
        #pragma unroll
        for (int c = 0; c < 4; c++) acc[r][c] = 0ull;

    #pragma unroll 4
    for (int k = 0; k < EMB; k++) {
        const float* ak = Hs + k * 33 + ty * 2;
        float a0 = ak[0], a1 = ak[1];
        const u64* wp = (const u64*)(Ws + k * 132 + tx * 8);
        u64 b0 = wp[0], b1 = wp[1], b2 = wp[2], b3 = wp[3];
        u64 A0 = pk2(a0, a0), A1 = pk2(a1, a1);
        acc[0][0]=fma2(A0,b0,acc[0][0]); acc[0][1]=fma2(A0,b1,acc[0][1]);
        acc[0][2]=fma2(A0,b2,acc[0][2]); acc[0][3]=fma2(A0,b3,acc[0][3]);
        acc[1][0]=fma2(A1,b0,acc[1][0]); acc[1][1]=fma2(A1,b1,acc[1][1]);
        acc[1][2]=fma2(A1,b2,acc[1][2]); acc[1][3]=fma2(A1,b3,acc[1][3]);
    }

    float* Hout = (layer == 0) ? g_H2 : g_H3;
    float vo[2][8];
    #pragma unroll
    for (int r = 0; r < 2; r++) {
        int row = r0 + ty * 2 + r;
        #pragma unroll
        for (int cp = 0; cp < 4; cp++) {
            float2 f = upk2(acc[r][cp]);
            #pragma unroll
            for (int hh = 0; hh < 2; hh++) {
                int col = tx * 8 + cp * 2 + hh;
                float v = (hh ? f.y : f.x) + (col < EMB ? bias[col] : 0.f);
                if (rout) v = fmaxf(v, 0.f);
                vo[r][cp * 2 + hh] = v;
                if (col < EMB) {
                    if (layer == 2) dout[((size_t)p * BR + row) * EMB + col] = v;
                    else            Hout[((size_t)p * BR + row) * EMB + col] = v;
                }
            }
        }
    }
    if (layer < 2) {
        #pragma unroll
        for (int c = 0; c < 8; c++)
            red[ty * 128 + tx * 8 + c] = vo[0][c] + vo[1][c];
        __syncthreads();
        if (t < 128) {
            float s = 0.f;
            #pragma unroll
            for (int g = 0; g < 16; g++) s += red[g * 128 + t];
            if (t < EMB) g_P[layer + 1][p][tile][0][t] = s;
        }
        __syncthreads();
        #pragma unroll
        for (int c = 0; c < 8; c++)
            red[ty * 128 + tx * 8 + c] = vo[0][c]*vo[0][c] + vo[1][c]*vo[1][c];
        __syncthreads();
        if (t < 128) {
            float s = 0.f;
            #pragma unroll
            for (int g = 0; g < 16; g++) s += red[g * 128 + t];
            if (t < EMB) g_P[layer + 1][p][tile][1][t] = s;
        }
    }
}

// ---------------- launch ----------------
extern "C" void kernel_launch(void* const* d_in, const int* in_sizes, int n_in,
                              void* d_out, int out_size)
{
    const float* x   = (const float*)d_in[0];
    const void*  mk  = d_in[1];
    const float* xr  = (const float*)d_in[2];
    const float* w1  = (const float*)d_in[3];
    const float* b1  = (const float*)d_in[4];
    const float* g1  = (const float*)d_in[5];
    const float* be1 = (const float*)d_in[6];
    const float* w2  = (const float*)d_in[7];
    const float* b2  = (const float*)d_in[8];
    const float* g2  = (const float*)d_in[9];
    const float* be2 = (const float*)d_in[10];
    const float* hw1 = (const float*)d_in[11];
    const float* hb1 = (const float*)d_in[12];
    const float* hg1 = (const float*)d_in[13];
    const float* hbe1= (const float*)d_in[14];
    const float* hw2 = (const float*)d_in[15];
    const float* hb2 = (const float*)d_in[16];
    float* out = (float*)d_out;

    cudaFuncSetAttribute(k_big,   cudaFuncAttributeMaxDynamicSharedMemorySize, NSTG * STG);
    cudaFuncSetAttribute(k_small, cudaFuncAttributeMaxDynamicSharedMemorySize, 76816);

    const int H = NPAD * MF / 2 / 2;
    k_detect<<<1, 256>>>((const unsigned char*)mk);          // 1
    k_wcvt<<<(H + 255) / 256, 256>>>(w1, 0);                 // 2
    k_wcvt<<<(H + 255) / 256, 256>>>(w1, H);                 // 3
    k_big<<<512, 256, NSTG * STG>>>(x, mk, xr);              // 4 <- profiled
    k_merge<<<dim3(64, 2), 256>>>(b1);                       // 5
    k_stats<<<2, 256>>>(0, g1, be1, 64);
    k_small<<<dim3(128, 2), 256, 76816>>>(0, w2, b2, nullptr);
    k_stats<<<2, 256>>>(1, g2, be2, 128);
    k_small<<<dim3(128, 2), 256, 76816>>>(1, hw1, hb1, nullptr);
    k_stats<<<2, 256>>>(2, hg1, hbe1, 128);
    k_small<<<dim3(128, 2), 256, 76816>>>(2, hw2, hb2, out);
}